// round 16
// baseline (speedup 1.0000x reference)
#include <cuda_runtime.h>
#include <cuda_bf16.h>
#include <cstdint>

#define BB 8
#define SS 2048
#define DD 256
#define ADIM 64
#define BM 64
#define BN 128
#define NT 16          // SS/BN
#define THREADS 256

#define XS2 528        // Q/K smem row stride bytes
#define PS2 144        // P smem row stride bytes (64-key half buffer)

// smem byte offsets
#define SM_QHI 0
#define SM_QLO 33792
#define SM_KHI 67584           // 128 rows x 528
#define SM_KLO 135168
#define SM_PHI 202752          // 64 rows x 144
#define SM_PLO 211968
#define SM_RS  221184          // [4][64] fp32
#define SMEM_BYTES 222208

__device__ __nv_bfloat16 g_xhi[BB * SS * DD];
__device__ __nv_bfloat16 g_xlo[BB * SS * DD];

#define LDSM4(r, a) \
    asm volatile("ldmatrix.sync.aligned.m8n8.x4.shared.b16 {%0,%1,%2,%3}, [%4];" \
                 : "=r"((r)[0]), "=r"((r)[1]), "=r"((r)[2]), "=r"((r)[3]) : "r"(a))
#define LDSM4T(r, a) \
    asm volatile("ldmatrix.sync.aligned.m8n8.x4.trans.shared.b16 {%0,%1,%2,%3}, [%4];" \
                 : "=r"((r)[0]), "=r"((r)[1]), "=r"((r)[2]), "=r"((r)[3]) : "r"(a))

__device__ __forceinline__ void mma16816(float* c, const uint32_t* a, uint32_t b0, uint32_t b1) {
    asm volatile("mma.sync.aligned.m16n8k16.row.col.f32.bf16.bf16.f32 "
                 "{%0,%1,%2,%3}, {%4,%5,%6,%7}, {%8,%9}, {%0,%1,%2,%3};"
                 : "+f"(c[0]), "+f"(c[1]), "+f"(c[2]), "+f"(c[3])
                 : "r"(a[0]), "r"(a[1]), "r"(a[2]), "r"(a[3]), "r"(b0), "r"(b1));
}

__device__ __forceinline__ uint32_t smem_u32(const void* p) {
    uint32_t a;
    asm("{ .reg .u64 t; cvta.to.shared.u64 t, %1; cvt.u32.u64 %0, t; }" : "=r"(a) : "l"(p));
    return a;
}
__device__ __forceinline__ void cp_async16(uint32_t saddr, const void* gptr) {
    asm volatile("cp.async.cg.shared.global [%0], [%1], 16;\n" :: "r"(saddr), "l"(gptr));
}
__device__ __forceinline__ void cp_commit() { asm volatile("cp.async.commit_group;\n" ::: "memory"); }
__device__ __forceinline__ void cp_wait0()  { asm volatile("cp.async.wait_group 0;\n" ::: "memory"); }

__device__ __forceinline__ void split2(float a, float b, uint32_t& hi, uint32_t& lo) {
    __nv_bfloat162 h = __floats2bfloat162_rn(a, b);
    __nv_bfloat162 l = __floats2bfloat162_rn(a - __bfloat162float(h.x), b - __bfloat162float(h.y));
    hi = *reinterpret_cast<uint32_t*>(&h);
    lo = *reinterpret_cast<uint32_t*>(&l);
}

// ---------------- kernel A: x fp32 -> bf16 hi/lo split ----------------
__global__ __launch_bounds__(256, 4)
void vs_conv_kernel(const float* __restrict__ x)
{
    int i = blockIdx.x * 256 + threadIdx.x;
    float4 v = ((const float4*)x)[i];
    uint32_t h0, l0, h1, l1;
    split2(v.x, v.y, h0, l0);
    split2(v.z, v.w, h1, l1);
    uint2 h; h.x = h0; h.y = h1;
    uint2 l; l.x = l0; l.y = l1;
    ((uint2*)g_xhi)[i] = h;
    ((uint2*)g_xlo)[i] = l;
}

// ---------------- kernel B: attention + projections ----------------
__global__ __launch_bounds__(THREADS, 1)
void vs_mma_kernel(const float* __restrict__ Wm, const float* __restrict__ bmb,
                   const float* __restrict__ Wl, const float* __restrict__ blb,
                   const float* __restrict__ eps, float* __restrict__ out)
{
    extern __shared__ __align__(128) char smem[];
    const int b = blockIdx.y, qt = blockIdx.x, t = threadIdx.x;
    const int w = t >> 5, lane = t & 31;
    const int rg = w & 1;          // 32-row group
    const int cg = w >> 1;         // 0..3: S 32-key group / PV 64-feat quarter
    const int quad = lane & 3;

    const char* gxh = (const char*)g_xhi + (size_t)b * SS * DD * 2;
    const char* gxl = (const char*)g_xlo + (size_t)b * SS * DD * 2;

    // prologue: issue Q tile loads (64 rows, hi+lo)
    {
        const char* qh = gxh + (size_t)qt * BM * DD * 2;
        const char* ql = gxl + (size_t)qt * BM * DD * 2;
        #pragma unroll
        for (int k = 0; k < 8; k++) {
            int i = t + k * THREADS;            // 2048 chunks per precision
            int r = i >> 5, c = i & 31;
            cp_async16(smem_u32(smem + SM_QHI + r * XS2 + c * 16), qh + r * 512 + c * 16);
            cp_async16(smem_u32(smem + SM_QLO + r * XS2 + c * 16), ql + r * 512 + c * 16);
        }
        cp_commit();
    }

    const uint32_t sQhi = smem_u32(smem + SM_QHI), sQlo = smem_u32(smem + SM_QLO);
    const uint32_t sKhi = smem_u32(smem + SM_KHI), sKlo = smem_u32(smem + SM_KLO);
    const uint32_t sPhi = smem_u32(smem + SM_PHI), sPlo = smem_u32(smem + SM_PLO);

    const int lrow = ((lane >> 3) & 1) * 8 + (lane & 7);
    const int lcol = (lane >> 4) * 16;
    const uint32_t aoff0 = (uint32_t)(rg * 32 + lrow) * XS2 + lcol;          // Q rows rt0
    const uint32_t aoff1 = aoff0 + 16 * XS2;                                  // Q rows rt1
    const uint32_t boff0 = (uint32_t)(cg * 32 + lrow) * XS2 + lcol;          // keys lo 16
    const uint32_t boff1 = boff0 + 16 * XS2;                                  // keys hi 16
    const uint32_t pa0   = (uint32_t)(rg * 32 + lrow) * PS2 + lcol;          // P rows rt0
    const uint32_t pa1   = pa0 + 16 * PS2;                                    // P rows rt1
    const uint32_t vrow0 = (uint32_t)lrow * XS2;
    const uint32_t vcolb = (uint32_t)(cg * 128 + (lane >> 4) * 16);          // feat quarter

    float o[16][4];                 // [rt*8 + np*2 + h][4] : rows 32, feats 64
    #pragma unroll
    for (int i = 0; i < 16; i++)
        #pragma unroll
        for (int j = 0; j < 4; j++) o[i][j] = 0.f;
    float rsv[4] = {0.f, 0.f, 0.f, 0.f};    // [rt*2 + rowhalf]
    const int r4 = lane >> 2;

    for (int kt = 0; kt < NT; kt++) {
        __syncthreads();                       // prev PV done with K/P buffers
        // load K tile kt (128 keys, hi+lo), single-buffered
        {
            const char* kh = gxh + (size_t)kt * BN * DD * 2;
            const char* kl = gxl + (size_t)kt * BN * DD * 2;
            #pragma unroll
            for (int k = 0; k < 16; k++) {
                int i = t + k * THREADS;        // 4096 chunks per precision
                int r = i >> 5, c = i & 31;
                cp_async16(smem_u32(smem + SM_KHI + r * XS2 + c * 16), kh + r * 512 + c * 16);
                cp_async16(smem_u32(smem + SM_KLO + r * XS2 + c * 16), kl + r * 512 + c * 16);
            }
            cp_commit();
            cp_wait0();
        }
        __syncthreads();

        // ---- S = Q K^T : warp tile 32 rows x 32 keys, bf16x3 ----
        float sc[8][4];                // [rt*4 + ktile*2 + nh]
        #pragma unroll
        for (int i = 0; i < 8; i++)
            #pragma unroll
            for (int j = 0; j < 4; j++) sc[i][j] = 0.f;

        #pragma unroll
        for (int ks = 0; ks < 16; ks++) {
            uint32_t aH0[4], aH1[4], aL0[4], aL1[4], b0[4], b1[4];
            LDSM4(aH0, sQhi + aoff0 + ks * 32);
            LDSM4(aH1, sQhi + aoff1 + ks * 32);
            LDSM4(aL0, sQlo + aoff0 + ks * 32);
            LDSM4(aL1, sQlo + aoff1 + ks * 32);
            LDSM4(b0, sKhi + boff0 + ks * 32);
            LDSM4(b1, sKhi + boff1 + ks * 32);
            mma16816(sc[0], aH0, b0[0], b0[2]);
            mma16816(sc[1], aH0, b0[1], b0[3]);
            mma16816(sc[2], aH0, b1[0], b1[2]);
            mma16816(sc[3], aH0, b1[1], b1[3]);
            mma16816(sc[4], aH1, b0[0], b0[2]);
            mma16816(sc[5], aH1, b0[1], b0[3]);
            mma16816(sc[6], aH1, b1[0], b1[2]);
            mma16816(sc[7], aH1, b1[1], b1[3]);
            mma16816(sc[0], aL0, b0[0], b0[2]);
            mma16816(sc[1], aL0, b0[1], b0[3]);
            mma16816(sc[2], aL0, b1[0], b1[2]);
            mma16816(sc[3], aL0, b1[1], b1[3]);
            mma16816(sc[4], aL1, b0[0], b0[2]);
            mma16816(sc[5], aL1, b0[1], b0[3]);
            mma16816(sc[6], aL1, b1[0], b1[2]);
            mma16816(sc[7], aL1, b1[1], b1[3]);
            LDSM4(b0, sKlo + boff0 + ks * 32);
            LDSM4(b1, sKlo + boff1 + ks * 32);
            mma16816(sc[0], aH0, b0[0], b0[2]);
            mma16816(sc[1], aH0, b0[1], b0[3]);
            mma16816(sc[2], aH0, b1[0], b1[2]);
            mma16816(sc[3], aH0, b1[1], b1[3]);
            mma16816(sc[4], aH1, b0[0], b0[2]);
            mma16816(sc[5], aH1, b0[1], b0[3]);
            mma16816(sc[6], aH1, b1[0], b1[2]);
            mma16816(sc[7], aH1, b1[1], b1[3]);
        }

        // ---- exp, rowsum partials, split P to regs ----
        uint32_t ph[8], pl[8], ph2[8], pl2[8];   // [rt*4 + j]
        #pragma unroll
        for (int i = 0; i < 8; i++) {
            int rt = i >> 2;
            float p0 = __expf(sc[i][0] * 0.0625f);
            float p1 = __expf(sc[i][1] * 0.0625f);
            float p2 = __expf(sc[i][2] * 0.0625f);
            float p3 = __expf(sc[i][3] * 0.0625f);
            rsv[rt * 2] += p0 + p1;  rsv[rt * 2 + 1] += p2 + p3;
            split2(p0, p1, ph[i], pl[i]);
            split2(p2, p3, ph2[i], pl2[i]);
        }

        #pragma unroll
        for (int half = 0; half < 2; half++) {
            // store P for this key half (cg 0,1 own keys 0..63; cg 2,3 keys 64..127)
            if ((cg >> 1) == half) {
                #pragma unroll
                for (int i = 0; i < 8; i++) {
                    int rt = i >> 2, j = i & 3;
                    uint32_t cb = (uint32_t)(((cg & 1) * 32 + j * 8 + 2 * quad)) * 2;
                    uint32_t rb = (uint32_t)(rg * 32 + rt * 16 + r4) * PS2 + cb;
                    *(uint32_t*)(smem + SM_PHI + rb) = ph[i];
                    *(uint32_t*)(smem + SM_PLO + rb) = pl[i];
                    *(uint32_t*)(smem + SM_PHI + rb + 8 * PS2) = ph2[i];
                    *(uint32_t*)(smem + SM_PLO + rb + 8 * PS2) = pl2[i];
                }
            }
            __syncthreads();

            // ---- PV: O += P(half keys) V(half keys, feat quarter) ----
            const uint32_t khb = (uint32_t)(half * 64);
            #pragma unroll
            for (int ks = 0; ks < 4; ks++) {
                uint32_t pH0[4], pH1[4], pL0[4], pL1[4];
                LDSM4(pH0, sPhi + pa0 + ks * 32);
                LDSM4(pH1, sPhi + pa1 + ks * 32);
                LDSM4(pL0, sPlo + pa0 + ks * 32);
                LDSM4(pL1, sPlo + pa1 + ks * 32);
                #pragma unroll
                for (int np = 0; np < 4; np++) {
                    uint32_t vH[4], vL[4];
                    uint32_t va = (khb + ks * 16) * XS2 + vrow0 + vcolb + np * 32;
                    LDSM4T(vH, sKhi + va);
                    LDSM4T(vL, sKlo + va);
                    mma16816(o[np * 2],     pH0, vH[0], vH[1]);
                    mma16816(o[np * 2 + 1], pH0, vH[2], vH[3]);
                    mma16816(o[np * 2],     pH0, vL[0], vL[1]);
                    mma16816(o[np * 2 + 1], pH0, vL[2], vL[3]);
                    mma16816(o[np * 2],     pL0, vH[0], vH[1]);
                    mma16816(o[np * 2 + 1], pL0, vH[2], vH[3]);
                    mma16816(o[8 + np * 2],     pH1, vH[0], vH[1]);
                    mma16816(o[8 + np * 2 + 1], pH1, vH[2], vH[3]);
                    mma16816(o[8 + np * 2],     pH1, vL[0], vL[1]);
                    mma16816(o[8 + np * 2 + 1], pH1, vL[2], vL[3]);
                    mma16816(o[8 + np * 2],     pL1, vH[0], vH[1]);
                    mma16816(o[8 + np * 2 + 1], pL1, vH[2], vH[3]);
                }
            }
            __syncthreads();
        }
    }

    // ---- rowsum reduce: quads, then 4 col-groups via smem ----
    #pragma unroll
    for (int i = 0; i < 4; i++) {
        rsv[i] += __shfl_xor_sync(0xffffffffu, rsv[i], 1);
        rsv[i] += __shfl_xor_sync(0xffffffffu, rsv[i], 2);
    }
    float* rsm = (float*)(smem + SM_RS);       // [4][64]
    if (quad == 0) {
        #pragma unroll
        for (int rt = 0; rt < 2; rt++) {
            rsm[cg * 64 + rg * 32 + rt * 16 + r4] = rsv[rt * 2];
            rsm[cg * 64 + rg * 32 + rt * 16 + r4 + 8] = rsv[rt * 2 + 1];
        }
    }
    __syncthreads();

    float inv[4];
    #pragma unroll
    for (int rt = 0; rt < 2; rt++) {
        int rl = rg * 32 + rt * 16 + r4;
        inv[rt * 2]     = 1.f / (rsm[rl] + rsm[64 + rl] + rsm[128 + rl] + rsm[192 + rl]);
        inv[rt * 2 + 1] = 1.f / (rsm[rl + 8] + rsm[64 + rl + 8] + rsm[128 + rl + 8] + rsm[192 + rl + 8]);
    }
    __syncthreads();

    // ---- A_det fp32 -> smem [64][260] (reuses Q region) ----
    float* Ad = (float*)smem;
    #pragma unroll
    for (int rt = 0; rt < 2; rt++) {
        int rl = rg * 32 + rt * 16 + r4;
        #pragma unroll
        for (int np = 0; np < 4; np++)
            #pragma unroll
            for (int h = 0; h < 2; h++) {
                int col = cg * 64 + np * 16 + h * 8 + 2 * quad;
                float* oo = o[rt * 8 + np * 2 + h];
                Ad[rl * 260 + col]     = oo[0] * inv[rt * 2];
                Ad[rl * 260 + col + 1] = oo[1] * inv[rt * 2];
                Ad[(rl + 8) * 260 + col]     = oo[2] * inv[rt * 2 + 1];
                Ad[(rl + 8) * 260 + col + 1] = oo[3] * inv[rt * 2 + 1];
            }
    }
    __syncthreads();

    // ---- SIMT projections + reparam epilogue: 4 rows x 4 cols/thread ----
    const int ty = t >> 4, tx = t & 15;
    float am[4][4], al[4][4];
    #pragma unroll
    for (int i = 0; i < 4; i++)
        #pragma unroll
        for (int j = 0; j < 4; j++) { am[i][j] = 0.f; al[i][j] = 0.f; }

    const float4* wm4 = (const float4*)Wm;
    const float4* wl4 = (const float4*)Wl;
    #pragma unroll 4
    for (int k = 0; k < DD; k++) {
        float4 m4 = wm4[k * 16 + tx];
        float4 l4 = wl4[k * 16 + tx];
        #pragma unroll
        for (int i = 0; i < 4; i++) {
            float a = Ad[(ty * 4 + i) * 260 + k];
            am[i][0] += a * m4.x; am[i][1] += a * m4.y; am[i][2] += a * m4.z; am[i][3] += a * m4.w;
            al[i][0] += a * l4.x; al[i][1] += a * l4.y; al[i][2] += a * l4.z; al[i][3] += a * l4.w;
        }
    }

    const size_t BSA = (size_t)BB * SS * ADIM;
    float4 bm4 = ((const float4*)bmb)[tx];
    float4 bl4 = ((const float4*)blb)[tx];
    #pragma unroll
    for (int i = 0; i < 4; i++) {
        int row = qt * BM + ty * 4 + i;
        size_t base = (((size_t)b * SS + row) * ADIM) + tx * 4;
        float4 e4 = *((const float4*)(eps + base));
        float4 mo, lo, ao;
        mo.x = am[i][0] + bm4.x; mo.y = am[i][1] + bm4.y; mo.z = am[i][2] + bm4.z; mo.w = am[i][3] + bm4.w;
        lo.x = al[i][0] + bl4.x; lo.y = al[i][1] + bl4.y; lo.z = al[i][2] + bl4.z; lo.w = al[i][3] + bl4.w;
        ao.x = mo.x + __expf(0.5f * lo.x) * e4.x;
        ao.y = mo.y + __expf(0.5f * lo.y) * e4.y;
        ao.z = mo.z + __expf(0.5f * lo.z) * e4.z;
        ao.w = mo.w + __expf(0.5f * lo.w) * e4.w;
        *((float4*)(out + base)) = mo;
        *((float4*)(out + BSA + base)) = lo;
        *((float4*)(out + 2 * BSA + base)) = ao;
    }
}

extern "C" void kernel_launch(void* const* d_in, const int* in_sizes, int n_in,
                              void* d_out, int out_size)
{
    const float* x   = (const float*)d_in[0];
    const float* Wm  = (const float*)d_in[1];
    const float* bmb = (const float*)d_in[2];
    const float* Wl  = (const float*)d_in[3];
    const float* blb = (const float*)d_in[4];
    const float* eps = (const float*)d_in[5];

    vs_conv_kernel<<<BB * SS * DD / 4 / 256, 256>>>(x);

    cudaFuncSetAttribute(vs_mma_kernel, cudaFuncAttributeMaxDynamicSharedMemorySize, SMEM_BYTES);
    dim3 grid(SS / BM, BB);
    vs_mma_kernel<<<grid, THREADS, SMEM_BYTES>>>(Wm, bmb, Wl, blb, eps, (float*)d_out);
}

// round 17
// speedup vs baseline: 1.0054x; 1.0054x over previous
#include <cuda_runtime.h>
#include <cuda_bf16.h>
#include <cstdint>

#define BB 8
#define SS 2048
#define DD 256
#define ADIM 64
#define BM 64
#define BN 128
#define NT 16          // SS/BN
#define THREADS 512

#define XS2 528        // Q/K smem row stride bytes
#define PS2 144        // P smem row stride bytes (64-key half)

// smem byte offsets
#define SM_QHI 0
#define SM_QLO 33792
#define SM_KHI 67584           // 128 rows x 528
#define SM_KLO 135168
#define SM_PHI 202752
#define SM_PLO 211968
#define SM_RS  221184
#define SMEM_BYTES 222208

__device__ __nv_bfloat16 g_xhi[BB * SS * DD];
__device__ __nv_bfloat16 g_xlo[BB * SS * DD];

#define LDSM4(r, a) \
    asm volatile("ldmatrix.sync.aligned.m8n8.x4.shared.b16 {%0,%1,%2,%3}, [%4];" \
                 : "=r"((r)[0]), "=r"((r)[1]), "=r"((r)[2]), "=r"((r)[3]) : "r"(a))
#define LDSM4T(r, a) \
    asm volatile("ldmatrix.sync.aligned.m8n8.x4.trans.shared.b16 {%0,%1,%2,%3}, [%4];" \
                 : "=r"((r)[0]), "=r"((r)[1]), "=r"((r)[2]), "=r"((r)[3]) : "r"(a))

__device__ __forceinline__ void mma16816(float* c, const uint32_t* a, uint32_t b0, uint32_t b1) {
    asm volatile("mma.sync.aligned.m16n8k16.row.col.f32.bf16.bf16.f32 "
                 "{%0,%1,%2,%3}, {%4,%5,%6,%7}, {%8,%9}, {%0,%1,%2,%3};"
                 : "+f"(c[0]), "+f"(c[1]), "+f"(c[2]), "+f"(c[3])
                 : "r"(a[0]), "r"(a[1]), "r"(a[2]), "r"(a[3]), "r"(b0), "r"(b1));
}

__device__ __forceinline__ uint32_t smem_u32(const void* p) {
    uint32_t a;
    asm("{ .reg .u64 t; cvta.to.shared.u64 t, %1; cvt.u32.u64 %0, t; }" : "=r"(a) : "l"(p));
    return a;
}
__device__ __forceinline__ void cp_async16(uint32_t saddr, const void* gptr) {
    asm volatile("cp.async.cg.shared.global [%0], [%1], 16;\n" :: "r"(saddr), "l"(gptr));
}
__device__ __forceinline__ void cp_commit() { asm volatile("cp.async.commit_group;\n" ::: "memory"); }
__device__ __forceinline__ void cp_wait0()  { asm volatile("cp.async.wait_group 0;\n" ::: "memory"); }

__device__ __forceinline__ void split2(float a, float b, uint32_t& hi, uint32_t& lo) {
    __nv_bfloat162 h = __floats2bfloat162_rn(a, b);
    __nv_bfloat162 l = __floats2bfloat162_rn(a - __bfloat162float(h.x), b - __bfloat162float(h.y));
    hi = *reinterpret_cast<uint32_t*>(&h);
    lo = *reinterpret_cast<uint32_t*>(&l);
}

// ---------------- kernel A: x fp32 -> bf16 hi/lo split ----------------
__global__ __launch_bounds__(256, 4)
void vs_conv_kernel(const float* __restrict__ x)
{
    int i = blockIdx.x * 256 + threadIdx.x;
    float4 v = ((const float4*)x)[i];
    uint32_t h0, l0, h1, l1;
    split2(v.x, v.y, h0, l0);
    split2(v.z, v.w, h1, l1);
    uint2 h; h.x = h0; h.y = h1;
    uint2 l; l.x = l0; l.y = l1;
    ((uint2*)g_xhi)[i] = h;
    ((uint2*)g_xlo)[i] = l;
}

// ---------------- kernel B: attention + projections ----------------
__global__ __launch_bounds__(THREADS, 1)
void vs_mma_kernel(const float* __restrict__ Wm, const float* __restrict__ bmb,
                   const float* __restrict__ Wl, const float* __restrict__ blb,
                   const float* __restrict__ eps, float* __restrict__ out)
{
    extern __shared__ __align__(128) char smem[];
    const int b = blockIdx.y, qt = blockIdx.x, t = threadIdx.x;
    const int w = t >> 5, lane = t & 31;
    const int rg = w & 3;          // 16-row group
    const int cg = w >> 2;         // S: 32-col group / PV: 64-feat quarter
    const int quad = lane & 3;

    const char* gxh = (const char*)g_xhi + (size_t)b * SS * DD * 2;
    const char* gxl = (const char*)g_xlo + (size_t)b * SS * DD * 2;

    // prologue: Q tile + full K tile 0 (hi+lo), one group
    {
        const char* qh = gxh + (size_t)qt * BM * DD * 2;
        const char* ql = gxl + (size_t)qt * BM * DD * 2;
        #pragma unroll
        for (int k = 0; k < 4; k++) {
            int i = t + k * THREADS;            // 2048 chunks per precision
            int r = i >> 5, c = i & 31;
            cp_async16(smem_u32(smem + SM_QHI + r * XS2 + c * 16), qh + r * 512 + c * 16);
            cp_async16(smem_u32(smem + SM_QLO + r * XS2 + c * 16), ql + r * 512 + c * 16);
        }
        #pragma unroll
        for (int k = 0; k < 8; k++) {
            int i = t + k * THREADS;            // 4096 chunks per precision
            int r = i >> 5, c = i & 31;
            cp_async16(smem_u32(smem + SM_KHI + r * XS2 + c * 16), gxh + r * 512 + c * 16);
            cp_async16(smem_u32(smem + SM_KLO + r * XS2 + c * 16), gxl + r * 512 + c * 16);
        }
        cp_commit();
        cp_wait0();
    }
    __syncthreads();

    const uint32_t sQhi = smem_u32(smem + SM_QHI), sQlo = smem_u32(smem + SM_QLO);
    const uint32_t sKhi = smem_u32(smem + SM_KHI), sKlo = smem_u32(smem + SM_KLO);
    const uint32_t sPhi = smem_u32(smem + SM_PHI), sPlo = smem_u32(smem + SM_PLO);

    const int lrow = ((lane >> 3) & 1) * 8 + (lane & 7);
    const int lcol = (lane >> 4) * 16;
    const uint32_t aoff  = (uint32_t)(rg * 16 + lrow) * XS2 + lcol;          // Q rows
    const uint32_t boff0 = (uint32_t)(cg * 32 + lrow) * XS2 + lcol;          // K keys lo 16
    const uint32_t boff1 = boff0 + 16 * XS2;                                 // K keys hi 16
    const uint32_t paoff = (uint32_t)(rg * 16 + lrow) * PS2 + lcol;          // P rows
    const uint32_t vcol  = (uint32_t)(cg * 128 + (lane >> 4) * 16);          // feat quarter
    const uint32_t vrow0 = (uint32_t)lrow * XS2;

    float o[8][4];
    #pragma unroll
    for (int i = 0; i < 8; i++)
        #pragma unroll
        for (int j = 0; j < 4; j++) o[i][j] = 0.f;
    float rs0 = 0.f, rs1 = 0.f;
    const int prow0 = rg * 16 + (lane >> 2);

    for (int kt = 0; kt < NT; kt++) {
        // K(kt) fully resident here

        // ---- S = Q K^T : warp tile 16 x 32 (cols cg*32..+32), bf16x3 ----
        float sc[4][4];
        #pragma unroll
        for (int i = 0; i < 4; i++)
            #pragma unroll
            for (int j = 0; j < 4; j++) sc[i][j] = 0.f;

        #pragma unroll
        for (int ks = 0; ks < 16; ks++) {
            uint32_t aH[4], aL[4], b0[4], b1[4];
            LDSM4(aH, sQhi + aoff + ks * 32);
            LDSM4(aL, sQlo + aoff + ks * 32);
            LDSM4(b0, sKhi + boff0 + ks * 32);
            LDSM4(b1, sKhi + boff1 + ks * 32);
            mma16816(sc[0], aH, b0[0], b0[2]);
            mma16816(sc[1], aH, b0[1], b0[3]);
            mma16816(sc[2], aH, b1[0], b1[2]);
            mma16816(sc[3], aH, b1[1], b1[3]);
            mma16816(sc[0], aL, b0[0], b0[2]);
            mma16816(sc[1], aL, b0[1], b0[3]);
            mma16816(sc[2], aL, b1[0], b1[2]);
            mma16816(sc[3], aL, b1[1], b1[3]);
            LDSM4(b0, sKlo + boff0 + ks * 32);
            LDSM4(b1, sKlo + boff1 + ks * 32);
            mma16816(sc[0], aH, b0[0], b0[2]);
            mma16816(sc[1], aH, b0[1], b0[3]);
            mma16816(sc[2], aH, b1[0], b1[2]);
            mma16816(sc[3], aH, b1[1], b1[3]);
        }

        // ---- exp, rowsum partials, split P (kept in regs until store) ----
        uint32_t ph[4], pl[4], ph2[4], pl2[4];
        #pragma unroll
        for (int nt = 0; nt < 4; nt++) {
            float p0 = __expf(sc[nt][0] * 0.0625f);
            float p1 = __expf(sc[nt][1] * 0.0625f);
            float p2 = __expf(sc[nt][2] * 0.0625f);
            float p3 = __expf(sc[nt][3] * 0.0625f);
            rs0 += p0 + p1;  rs1 += p2 + p3;
            split2(p0, p1, ph[nt], pl[nt]);
            split2(p2, p3, ph2[nt], pl2[nt]);
        }

        const uint32_t cb0 = (uint32_t)((cg & 1) * 32);
        // store P for key-half 0 (warps cg<2 own keys 0..63)
        if (cg < 2) {
            #pragma unroll
            for (int nt = 0; nt < 4; nt++) {
                uint32_t cb = (cb0 + nt * 8 + 2 * quad) * 2;
                *(uint32_t*)(smem + SM_PHI + prow0 * PS2 + cb) = ph[nt];
                *(uint32_t*)(smem + SM_PLO + prow0 * PS2 + cb) = pl[nt];
                *(uint32_t*)(smem + SM_PHI + (prow0 + 8) * PS2 + cb) = ph2[nt];
                *(uint32_t*)(smem + SM_PLO + (prow0 + 8) * PS2 + cb) = pl2[nt];
            }
        }
        __syncthreads();

        // ---- PV half 0: O += P(keys 0..63) V(keys 0..63, feat quarter) ----
        #pragma unroll
        for (int ks = 0; ks < 4; ks++) {
            uint32_t pH[4], pL[4];
            LDSM4(pH, sPhi + paoff + ks * 32);
            LDSM4(pL, sPlo + paoff + ks * 32);
            #pragma unroll
            for (int np = 0; np < 4; np++) {
                uint32_t vH[4], vL[4];
                uint32_t va = (uint32_t)(ks * 16) * XS2 + vrow0 + vcol + np * 32;
                LDSM4T(vH, sKhi + va);
                LDSM4T(vL, sKlo + va);
                mma16816(o[np * 2], pH, vH[0], vH[1]);
                mma16816(o[np * 2], pH, vL[0], vL[1]);
                mma16816(o[np * 2], pL, vH[0], vH[1]);
                mma16816(o[np * 2 + 1], pH, vH[2], vH[3]);
                mma16816(o[np * 2 + 1], pH, vL[2], vL[3]);
                mma16816(o[np * 2 + 1], pL, vH[2], vH[3]);
            }
        }
        __syncthreads();   // all warps done reading keys 0..63 (and P half0)

        // pipelined load: next tile's keys 0..63 into the now-dead region,
        // overlapping P half-1 staging + PV half 1
        if (kt + 1 < NT) {
            const char* kh = gxh + (size_t)(kt + 1) * BN * DD * 2;
            const char* kl = gxl + (size_t)(kt + 1) * BN * DD * 2;
            #pragma unroll
            for (int k = 0; k < 4; k++) {
                int i = t + k * THREADS;        // 2048 chunks per precision
                int r = i >> 5, c = i & 31;
                cp_async16(smem_u32(smem + SM_KHI + r * XS2 + c * 16), kh + r * 512 + c * 16);
                cp_async16(smem_u32(smem + SM_KLO + r * XS2 + c * 16), kl + r * 512 + c * 16);
            }
            cp_commit();
        }

        // store P for key-half 1 (warps cg>=2 own keys 64..127)
        if (cg >= 2) {
            #pragma unroll
            for (int nt = 0; nt < 4; nt++) {
                uint32_t cb = (cb0 + nt * 8 + 2 * quad) * 2;
                *(uint32_t*)(smem + SM_PHI + prow0 * PS2 + cb) = ph[nt];
                *(uint32_t*)(smem + SM_PLO + prow0 * PS2 + cb) = pl[nt];
                *(uint32_t*)(smem + SM_PHI + (prow0 + 8) * PS2 + cb) = ph2[nt];
                *(uint32_t*)(smem + SM_PLO + (prow0 + 8) * PS2 + cb) = pl2[nt];
            }
        }
        __syncthreads();

        // ---- PV half 1: keys 64..127 ----
        #pragma unroll
        for (int ks = 0; ks < 4; ks++) {
            uint32_t pH[4], pL[4];
            LDSM4(pH, sPhi + paoff + ks * 32);
            LDSM4(pL, sPlo + paoff + ks * 32);
            #pragma unroll
            for (int np = 0; np < 4; np++) {
                uint32_t vH[4], vL[4];
                uint32_t va = (uint32_t)(64 + ks * 16) * XS2 + vrow0 + vcol + np * 32;
                LDSM4T(vH, sKhi + va);
                LDSM4T(vL, sKlo + va);
                mma16816(o[np * 2], pH, vH[0], vH[1]);
                mma16816(o[np * 2], pH, vL[0], vL[1]);
                mma16816(o[np * 2], pL, vH[0], vH[1]);
                mma16816(o[np * 2 + 1], pH, vH[2], vH[3]);
                mma16816(o[np * 2 + 1], pH, vL[2], vL[3]);
                mma16816(o[np * 2 + 1], pL, vH[2], vH[3]);
            }
        }
        __syncthreads();   // keys 64..127 now dead

        if (kt + 1 < NT) {
            const char* kh = gxh + ((size_t)(kt + 1) * BN + 64) * DD * 2;
            const char* kl = gxl + ((size_t)(kt + 1) * BN + 64) * DD * 2;
            #pragma unroll
            for (int k = 0; k < 4; k++) {
                int i = t + k * THREADS;
                int r = i >> 5, c = i & 31;
                cp_async16(smem_u32(smem + SM_KHI + (64 + r) * XS2 + c * 16), kh + r * 512 + c * 16);
                cp_async16(smem_u32(smem + SM_KLO + (64 + r) * XS2 + c * 16), kl + r * 512 + c * 16);
            }
            cp_commit();
            cp_wait0();                        // both halves of kt+1 landed
        }
        __syncthreads();                       // visible to all warps
    }

    // ---- rowsum reduce: quads, then 4 col-groups via smem ----
    rs0 += __shfl_xor_sync(0xffffffffu, rs0, 1);
    rs0 += __shfl_xor_sync(0xffffffffu, rs0, 2);
    rs1 += __shfl_xor_sync(0xffffffffu, rs1, 1);
    rs1 += __shfl_xor_sync(0xffffffffu, rs1, 2);
    float* rsm = (float*)(smem + SM_RS);       // [4][64]
    if (quad == 0) {
        rsm[cg * 64 + rg * 16 + (lane >> 2)] = rs0;
        rsm[cg * 64 + rg * 16 + (lane >> 2) + 8] = rs1;
    }
    __syncthreads();

    const int orow0 = rg * 16 + (lane >> 2);
    float inv0 = 1.f / (rsm[orow0] + rsm[64 + orow0] + rsm[128 + orow0] + rsm[192 + orow0]);
    float inv1 = 1.f / (rsm[orow0 + 8] + rsm[64 + orow0 + 8] + rsm[128 + orow0 + 8] + rsm[192 + orow0 + 8]);
    __syncthreads();

    // ---- A_det fp32 -> smem [64][260] (reuses Q region) ----
    float* Ad = (float*)smem;
    #pragma unroll
    for (int nt = 0; nt < 8; nt++) {
        int col = cg * 64 + nt * 8 + 2 * quad;
        Ad[orow0 * 260 + col] = o[nt][0] * inv0;
        Ad[orow0 * 260 + col + 1] = o[nt][1] * inv0;
        Ad[(orow0 + 8) * 260 + col] = o[nt][2] * inv1;
        Ad[(orow0 + 8) * 260 + col + 1] = o[nt][3] * inv1;
    }
    __syncthreads();

    // ---- SIMT projections + reparam epilogue: 2 rows x 4 cols/thread ----
    const int ty = t >> 4, tx = t & 15;
    float am[2][4], al[2][4];
    #pragma unroll
    for (int i = 0; i < 2; i++)
        #pragma unroll
        for (int j = 0; j < 4; j++) { am[i][j] = 0.f; al[i][j] = 0.f; }

    const float4* wm4 = (const float4*)Wm;
    const float4* wl4 = (const float4*)Wl;
    #pragma unroll 4
    for (int k = 0; k < DD; k++) {
        float4 m4 = wm4[k * 16 + tx];
        float4 l4 = wl4[k * 16 + tx];
        #pragma unroll
        for (int i = 0; i < 2; i++) {
            float a = Ad[(ty * 2 + i) * 260 + k];
            am[i][0] += a * m4.x; am[i][1] += a * m4.y; am[i][2] += a * m4.z; am[i][3] += a * m4.w;
            al[i][0] += a * l4.x; al[i][1] += a * l4.y; al[i][2] += a * l4.z; al[i][3] += a * l4.w;
        }
    }

    const size_t BSA = (size_t)BB * SS * ADIM;
    float4 bm4 = ((const float4*)bmb)[tx];
    float4 bl4 = ((const float4*)blb)[tx];
    #pragma unroll
    for (int i = 0; i < 2; i++) {
        int row = qt * BM + ty * 2 + i;
        size_t base = (((size_t)b * SS + row) * ADIM) + tx * 4;
        float4 e4 = *((const float4*)(eps + base));
        float4 mo, lo, ao;
        mo.x = am[i][0] + bm4.x; mo.y = am[i][1] + bm4.y; mo.z = am[i][2] + bm4.z; mo.w = am[i][3] + bm4.w;
        lo.x = al[i][0] + bl4.x; lo.y = al[i][1] + bl4.y; lo.z = al[i][2] + bl4.z; lo.w = al[i][3] + bl4.w;
        ao.x = mo.x + __expf(0.5f * lo.x) * e4.x;
        ao.y = mo.y + __expf(0.5f * lo.y) * e4.y;
        ao.z = mo.z + __expf(0.5f * lo.z) * e4.z;
        ao.w = mo.w + __expf(0.5f * lo.w) * e4.w;
        *((float4*)(out + base)) = mo;
        *((float4*)(out + BSA + base)) = lo;
        *((float4*)(out + 2 * BSA + base)) = ao;
    }
}

extern "C" void kernel_launch(void* const* d_in, const int* in_sizes, int n_in,
                              void* d_out, int out_size)
{
    const float* x   = (const float*)d_in[0];
    const float* Wm  = (const float*)d_in[1];
    const float* bmb = (const float*)d_in[2];
    const float* Wl  = (const float*)d_in[3];
    const float* blb = (const float*)d_in[4];
    const float* eps = (const float*)d_in[5];

    vs_conv_kernel<<<BB * SS * DD / 4 / 256, 256>>>(x);

    cudaFuncSetAttribute(vs_mma_kernel, cudaFuncAttributeMaxDynamicSharedMemorySize, SMEM_BYTES);
    dim3 grid(SS / BM, BB);
    vs_mma_kernel<<<grid, THREADS, SMEM_BYTES>>>(Wm, bmb, Wl, blb, eps, (float*)d_out);
}